// round 12
// baseline (speedup 1.0000x reference)
#include <cuda_runtime.h>
#include <cuda_bf16.h>
#include <cstdint>

#define B_  64
#define D_  128
#define LC  1024
#define LQ  256
#define FST 36       // fp32 smem row stride (144B: conflict-free STS.128 + ldmatrix)

// ---------------- scratch (static device arrays) ----------------
static __device__ float g_E   [(size_t)B_*LC*LQ];    // exp(S + biases), tf32-rounded
static __device__ float g_T   [(size_t)B_*LQ*D_];    // T_raw [m'][d] (unscaled)
static __device__ float g_rinv[B_*LC];
static __device__ float g_qcinv[B_*LQ];
static __device__ float g_cpart[B_*8*LQ];
static __device__ float g_c1[B_*LC];
static __device__ float g_q2[B_*LQ];

// ---------------- helpers ----------------
__device__ __forceinline__ uint32_t smem_u32(const void* p) {
    uint32_t a;
    asm("{ .reg .u64 t; cvta.to.shared.u64 t, %1; cvt.u32.u64 %0, t; }" : "=r"(a) : "l"(p));
    return a;
}

__device__ __forceinline__ float tf32r(float x) {
    uint32_t o; asm("cvt.rna.tf32.f32 %0, %1;" : "=r"(o) : "f"(x));
    return __uint_as_float(o);
}

#define LDSM_X4(r, a) \
    asm volatile("ldmatrix.sync.aligned.m8n8.x4.shared.b16 {%0,%1,%2,%3}, [%4];" \
        : "=r"((r)[0]), "=r"((r)[1]), "=r"((r)[2]), "=r"((r)[3]) : "r"(a))

#define MMA_TF32(c, a, b0, b1) \
    asm volatile("mma.sync.aligned.m16n8k8.row.col.f32.tf32.tf32.f32 " \
        "{%0,%1,%2,%3}, {%4,%5,%6,%7}, {%8,%9}, {%0,%1,%2,%3};" \
        : "+f"((c)[0]), "+f"((c)[1]), "+f"((c)[2]), "+f"((c)[3]) \
        : "r"((a)[0]), "r"((a)[1]), "r"((a)[2]), "r"((a)[3]), "r"(b0), "r"(b1))

__device__ __forceinline__ float4 maybe_cvt(const float4& x, bool docvt) {
    if (!docvt) return x;
    float4 t;
    t.x = tf32r(x.x); t.y = tf32r(x.y); t.z = tf32r(x.z); t.w = tf32r(x.w);
    return t;
}

// ---------------- 128-thread tgemm: BM=128, BN=64, warp tile 64x32 ----------------
// Out(m,n) = sum_k A(m,k)*B(n,k)
// AT/BT: TRANS; KSA/KSB: per-k scale; CVA/CVB: tf32-round at smem store; EPI: 0 plain, 1 exp+bias->E
template<bool AT, bool BT, bool KSA, bool KSB, bool CVA, bool CVB, int EPI>
__global__ __launch_bounds__(128, 3) void tgemm(
    const float* __restrict__ Ag, int lda, long batA,
    const float* __restrict__ Bg, int ldb, long batB,
    float* __restrict__ Cg, int ldc, long batC,
    int Kloc,
    const float* __restrict__ ksA, int ksAstr,
    const float* __restrict__ ksB, int ksBstr,
    const float* __restrict__ biasR, const float* __restrict__ biasC)
{
    __shared__ __align__(16) float sA[128 * FST];
    __shared__ __align__(16) float sB[64 * FST];

    const int zb = blockIdx.z;
    const int m0 = blockIdx.y << 7;
    const int n0 = blockIdx.x * 64;
    const float* Ab = Ag + (size_t)zb * batA;
    const float* Bb = Bg + (size_t)zb * batB;
    const float* kA = KSA ? (ksA + (size_t)zb * ksAstr) : nullptr;
    const float* kB = KSB ? (ksB + (size_t)zb * ksBstr) : nullptr;

    const int tid = threadIdx.x, wid = tid >> 5, lane = tid & 31;
    const int wm = (wid >> 1) * 64, wn = (wid & 1) * 32;

    float acc[4][4][4];
#pragma unroll
    for (int i = 0; i < 4; i++)
#pragma unroll
        for (int j = 0; j < 4; j++)
#pragma unroll
            for (int e = 0; e < 4; e++) acc[i][j][e] = 0.f;

    float4 ra[8], rb[4];

    auto ldgA = [&](int kk) {
#pragma unroll
        for (int i = 0; i < 8; i++) {
            int v = i * 128 + tid;
            if constexpr (!AT) {
                int row = v >> 3, c4 = v & 7;
                float4 x = *reinterpret_cast<const float4*>(Ab + (size_t)(m0 + row) * lda + kk + c4 * 4);
                if constexpr (KSA) {
                    float4 s = *reinterpret_cast<const float4*>(kA + kk + c4 * 4);
                    x.x *= s.x; x.y *= s.y; x.z *= s.z; x.w *= s.w;
                }
                ra[i] = x;
            } else {
                int mn = v & 127, krb = v >> 7;
                const float* p = Ab + (size_t)(kk + krb * 4) * lda + m0 + mn;
                float4 x;
                x.x = p[0]; x.y = p[lda]; x.z = p[2 * (size_t)lda]; x.w = p[3 * (size_t)lda];
                if constexpr (KSA) {
                    const float* s = kA + kk + krb * 4;
                    x.x *= s[0]; x.y *= s[1]; x.z *= s[2]; x.w *= s[3];
                }
                ra[i] = x;
            }
        }
    };
    auto ldgB = [&](int kk) {
#pragma unroll
        for (int i = 0; i < 4; i++) {
            int v = i * 128 + tid;
            if constexpr (!BT) {
                int row = v >> 3, c4 = v & 7;
                float4 x = *reinterpret_cast<const float4*>(Bb + (size_t)(n0 + row) * ldb + kk + c4 * 4);
                if constexpr (KSB) {
                    float4 s = *reinterpret_cast<const float4*>(kB + kk + c4 * 4);
                    x.x *= s.x; x.y *= s.y; x.z *= s.z; x.w *= s.w;
                }
                rb[i] = x;
            } else {
                int mn = v & 63, krb = v >> 6;
                const float* p = Bb + (size_t)(kk + krb * 4) * ldb + n0 + mn;
                float4 x;
                x.x = p[0]; x.y = p[ldb]; x.z = p[2 * (size_t)ldb]; x.w = p[3 * (size_t)ldb];
                if constexpr (KSB) {
                    const float* s = kB + kk + krb * 4;
                    x.x *= s[0]; x.y *= s[1]; x.z *= s[2]; x.w *= s[3];
                }
                rb[i] = x;
            }
        }
    };
    auto sts = [&]() {
#pragma unroll
        for (int i = 0; i < 8; i++) {
            int v = i * 128 + tid;
            int off;
            if constexpr (!AT) { int row = v >> 3, c4 = v & 7; off = row * FST + c4 * 4; }
            else               { int mn = v & 127, krb = v >> 7; off = mn * FST + krb * 4; }
            *reinterpret_cast<float4*>(sA + off) = maybe_cvt(ra[i], CVA);
        }
#pragma unroll
        for (int i = 0; i < 4; i++) {
            int v = i * 128 + tid;
            int off;
            if constexpr (!BT) { int row = v >> 3, c4 = v & 7; off = row * FST + c4 * 4; }
            else               { int mn = v & 63, krb = v >> 6; off = mn * FST + krb * 4; }
            *reinterpret_cast<float4*>(sB + off) = maybe_cvt(rb[i], CVB);
        }
    };

    const uint32_t bA = smem_u32(sA), bB = smem_u32(sB);
    const uint32_t lrow = (uint32_t)(lane & 15) * FST + ((lane >> 4) << 2);

    const int nch = Kloc >> 5;
    ldgA(0); ldgB(0);

    for (int ch = 0; ch < nch; ch++) {
        sts();
        __syncthreads();
        if (ch + 1 < nch) { ldgA((ch + 1) << 5); ldgB((ch + 1) << 5); }
#pragma unroll
        for (int ks = 0; ks < 4; ks++) {
            uint32_t af[4][4];
#pragma unroll
            for (int mt = 0; mt < 4; mt++) {
                uint32_t aoff = ((uint32_t)(wm + mt * 16) * FST + lrow + ks * 8) * 4u;
                LDSM_X4(af[mt], bA + aoff);
            }
            uint32_t bf[2][4];
#pragma unroll
            for (int nb = 0; nb < 2; nb++) {
                uint32_t boff = ((uint32_t)(wn + nb * 16) * FST + lrow + ks * 8) * 4u;
                LDSM_X4(bf[nb], bB + boff);
            }
#pragma unroll
            for (int mt = 0; mt < 4; mt++)
#pragma unroll
                for (int nb = 0; nb < 2; nb++) {
                    MMA_TF32(acc[mt][nb * 2 + 0], af[mt], bf[nb][0], bf[nb][2]);
                    MMA_TF32(acc[mt][nb * 2 + 1], af[mt], bf[nb][1], bf[nb][3]);
                }
        }
        __syncthreads();
    }

    float* Cb = Cg + (size_t)zb * batC;
#pragma unroll
    for (int mt = 0; mt < 4; mt++) {
        int r0 = m0 + wm + mt * 16 + (lane >> 2);
        int r1 = r0 + 8;
        float br0 = 0.f, br1 = 0.f;
        if constexpr (EPI == 1) { br0 = biasR[zb * LC + r0]; br1 = biasR[zb * LC + r1]; }
#pragma unroll
        for (int nt = 0; nt < 4; nt++) {
            int col = n0 + wn + nt * 8 + (lane & 3) * 2;
            float2 v0, v1;
            v0.x = acc[mt][nt][0]; v0.y = acc[mt][nt][1];
            v1.x = acc[mt][nt][2]; v1.y = acc[mt][nt][3];
            if constexpr (EPI == 1) {
                float bc0 = biasC[zb * LQ + col], bc1 = biasC[zb * LQ + col + 1];
                v0.x = tf32r(__expf(v0.x + br0 + bc0)); v0.y = tf32r(__expf(v0.y + br0 + bc1));
                v1.x = tf32r(__expf(v1.x + br1 + bc0)); v1.y = tf32r(__expf(v1.y + br1 + bc1));
            }
            *reinterpret_cast<float2*>(Cb + (size_t)r0 * ldc + col) = v0;
            *reinterpret_cast<float2*>(Cb + (size_t)r1 * ldc + col) = v1;
        }
    }
}

// ---------------- fused G2+G4: stacked A = [Q*qm ; T_raw*qcinv], B = E tile ----------------
__global__ __launch_bounds__(256) void g24(
    const float* __restrict__ Q, const float* __restrict__ T,
    const float* __restrict__ E, const float* __restrict__ C,
    const float* __restrict__ qmask, const float* __restrict__ qcinv,
    const float* __restrict__ rinv, float* __restrict__ out)
{
    __shared__ __align__(16) float sA[256 * FST];
    __shared__ __align__(16) float sB[64 * FST];

    const int zb = blockIdx.z;
    const int n0 = blockIdx.x * 64;
    const float* Qb = Q + (size_t)zb * D_ * LQ;
    const float* Tb = T + (size_t)zb * LQ * D_;
    const float* Eb = E + (size_t)zb * LC * LQ;
    const float* qm = qmask + zb * LQ;
    const float* qc = qcinv + zb * LQ;

    const int tid = threadIdx.x, wid = tid >> 5, lane = tid & 31;
    const int wm = (wid >> 1) * 64, wn = (wid & 1) * 32;

    float acc[4][4][4];
#pragma unroll
    for (int i = 0; i < 4; i++)
#pragma unroll
        for (int j = 0; j < 4; j++)
#pragma unroll
            for (int e = 0; e < 4; e++) acc[i][j][e] = 0.f;

    float4 ra[8], rb[2];

    auto ldgA = [&](int kk) {
#pragma unroll
        for (int i = 0; i < 4; i++) {                 // Q half, rows 0..127, K-fast
            int v = i * 256 + tid;
            int row = v >> 3, c4 = v & 7;
            float4 x = *reinterpret_cast<const float4*>(Qb + (size_t)row * LQ + kk + c4 * 4);
            float4 s = *reinterpret_cast<const float4*>(qm + kk + c4 * 4);
            x.x *= s.x; x.y *= s.y; x.z *= s.z; x.w *= s.w;
            ra[i] = x;
        }
#pragma unroll
        for (int i = 0; i < 4; i++) {                 // T half, rows 128..255, K-slow
            int v = i * 256 + tid;
            int mn = v & 127, krb = v >> 7;
            const float* p = Tb + (size_t)(kk + krb * 4) * D_ + mn;
            const float* s = qc + kk + krb * 4;
            float4 x;
            x.x = p[0] * s[0]; x.y = p[D_] * s[1];
            x.z = p[2 * D_] * s[2]; x.w = p[3 * D_] * s[3];
            ra[4 + i] = x;
        }
    };
    auto ldgB = [&](int kk) {
#pragma unroll
        for (int i = 0; i < 2; i++) {                 // E tile, 64 rows (l), K-fast
            int v = i * 256 + tid;
            int row = v >> 3, c4 = v & 7;
            rb[i] = *reinterpret_cast<const float4*>(Eb + (size_t)(n0 + row) * LQ + kk + c4 * 4);
        }
    };
    auto sts = [&]() {
#pragma unroll
        for (int i = 0; i < 4; i++) {
            int v = i * 256 + tid;
            int row = v >> 3, c4 = v & 7;
            *reinterpret_cast<float4*>(sA + row * FST + c4 * 4) = maybe_cvt(ra[i], true);
        }
#pragma unroll
        for (int i = 0; i < 4; i++) {
            int v = i * 256 + tid;
            int mn = v & 127, krb = v >> 7;
            *reinterpret_cast<float4*>(sA + (128 + mn) * FST + krb * 4) = maybe_cvt(ra[4 + i], true);
        }
#pragma unroll
        for (int i = 0; i < 2; i++) {                 // E pre-rounded: no cvt
            int v = i * 256 + tid;
            int row = v >> 3, c4 = v & 7;
            *reinterpret_cast<float4*>(sB + row * FST + c4 * 4) = rb[i];
        }
    };

    const uint32_t bA = smem_u32(sA), bB = smem_u32(sB);
    const uint32_t lrow = (uint32_t)(lane & 15) * FST + ((lane >> 4) << 2);

    const int nch = LQ >> 5;   // 8
    ldgA(0); ldgB(0);

    for (int ch = 0; ch < nch; ch++) {
        sts();
        __syncthreads();
        if (ch + 1 < nch) { ldgA((ch + 1) << 5); ldgB((ch + 1) << 5); }
#pragma unroll
        for (int ks = 0; ks < 4; ks++) {
            uint32_t af[4][4];
#pragma unroll
            for (int mt = 0; mt < 4; mt++) {
                uint32_t aoff = ((uint32_t)(wm + mt * 16) * FST + lrow + ks * 8) * 4u;
                LDSM_X4(af[mt], bA + aoff);
            }
            uint32_t bf[2][4];
#pragma unroll
            for (int nb = 0; nb < 2; nb++) {
                uint32_t boff = ((uint32_t)(wn + nb * 16) * FST + lrow + ks * 8) * 4u;
                LDSM_X4(bf[nb], bB + boff);
            }
#pragma unroll
            for (int mt = 0; mt < 4; mt++)
#pragma unroll
                for (int nb = 0; nb < 2; nb++) {
                    MMA_TF32(acc[mt][nb * 2 + 0], af[mt], bf[nb][0], bf[nb][2]);
                    MMA_TF32(acc[mt][nb * 2 + 1], af[mt], bf[nb][1], bf[nb][3]);
                }
        }
        __syncthreads();
    }

    // epilogue: rows < 128 => At (channels 0,1,2); rows >= 128 => Bv (channel 3)
    const float* Cb = C + (size_t)zb * D_ * LC;
    const float* rv = rinv + zb * LC;
    float* O = out + (size_t)zb * 4 * D_ * LC;
#pragma unroll
    for (int mt = 0; mt < 4; mt++) {
        int r0 = wm + mt * 16 + (lane >> 2);
        int r1 = r0 + 8;
#pragma unroll
        for (int nt = 0; nt < 4; nt++) {
            int col = n0 + wn + nt * 8 + (lane & 3) * 2;
            float c0 = rv[col], c1v = rv[col + 1];
            float2 v0, v1;
            v0.x = acc[mt][nt][0] * c0; v0.y = acc[mt][nt][1] * c1v;
            v1.x = acc[mt][nt][2] * c0; v1.y = acc[mt][nt][3] * c1v;
            if (wm < 128) {
                int d0 = r0, d1 = r1;
                float2 cc0 = *reinterpret_cast<const float2*>(Cb + (size_t)d0 * LC + col);
                float2 cc1 = *reinterpret_cast<const float2*>(Cb + (size_t)d1 * LC + col);
                *reinterpret_cast<float2*>(O + (size_t)d0 * LC + col) = cc0;
                *reinterpret_cast<float2*>(O + (size_t)d1 * LC + col) = cc1;
                *reinterpret_cast<float2*>(O + (size_t)(D_ + d0) * LC + col) = v0;
                *reinterpret_cast<float2*>(O + (size_t)(D_ + d1) * LC + col) = v1;
                float2 m0v, m1v;
                m0v.x = cc0.x * v0.x; m0v.y = cc0.y * v0.y;
                m1v.x = cc1.x * v1.x; m1v.y = cc1.y * v1.y;
                *reinterpret_cast<float2*>(O + (size_t)(2 * D_ + d0) * LC + col) = m0v;
                *reinterpret_cast<float2*>(O + (size_t)(2 * D_ + d1) * LC + col) = m1v;
            } else {
                int d0 = r0 - 128, d1 = r1 - 128;
                float2 cc0 = *reinterpret_cast<const float2*>(Cb + (size_t)d0 * LC + col);
                float2 cc1 = *reinterpret_cast<const float2*>(Cb + (size_t)d1 * LC + col);
                float2 b0v, b1v;
                b0v.x = cc0.x * v0.x; b0v.y = cc0.y * v0.y;
                b1v.x = cc1.x * v1.x; b1v.y = cc1.y * v1.y;
                *reinterpret_cast<float2*>(O + (size_t)(3 * D_ + d0) * LC + col) = b0v;
                *reinterpret_cast<float2*>(O + (size_t)(3 * D_ + d1) * LC + col) = b1v;
            }
        }
    }
}

// ---------------- K1: bias vectors c1[l] = Ct.w1, q2[m] = Qt.w2 ----------------
__global__ void k_bias(const float* __restrict__ C, const float* __restrict__ Q,
                       const float* __restrict__ w) {
    int b = blockIdx.y, seg = blockIdx.x, t = threadIdx.x;
    if (seg < 4) {
        int l = seg * 256 + t;
        const float* Cb = C + (size_t)b * D_ * LC;
        float acc = 0.f;
#pragma unroll 8
        for (int d = 0; d < D_; d++) acc += Cb[(size_t)d * LC + l] * __ldg(w + d);
        g_c1[b * LC + l] = acc;
    } else {
        int m = t;
        const float* Qb = Q + (size_t)b * D_ * LQ;
        float acc = 0.f;
#pragma unroll 8
        for (int d = 0; d < D_; d++) acc += Qb[(size_t)d * LQ + m] * __ldg(w + D_ + d);
        g_q2[b * LQ + m] = acc;
    }
}

// ---------------- sums: rinv[l] = 1/sum_m E*qm, col partials for cinv ----------------
__global__ __launch_bounds__(256) void k_sums(const float* __restrict__ qmask,
                                              const float* __restrict__ cmask) {
    int b = blockIdx.y, rc = blockIdx.x;
    int w = threadIdx.x >> 5, lane = threadIdx.x & 31;
    __shared__ float cp[8][256];
    float4 q0 = *reinterpret_cast<const float4*>(qmask + b * LQ + lane * 4);
    float4 q1 = *reinterpret_cast<const float4*>(qmask + b * LQ + 128 + lane * 4);
    float col[8] = {0.f, 0.f, 0.f, 0.f, 0.f, 0.f, 0.f, 0.f};
#pragma unroll 4
    for (int rr = 0; rr < 16; rr++) {
        int l = rc * 128 + w * 16 + rr;
        const float* Er = g_E + ((size_t)b * LC + l) * LQ;
        float4 e0 = *reinterpret_cast<const float4*>(Er + lane * 4);
        float4 e1 = *reinterpret_cast<const float4*>(Er + 128 + lane * 4);
        float cm = cmask[b * LC + l];
        col[0] += e0.x * cm; col[1] += e0.y * cm; col[2] += e0.z * cm; col[3] += e0.w * cm;
        col[4] += e1.x * cm; col[5] += e1.y * cm; col[6] += e1.z * cm; col[7] += e1.w * cm;
        float s = e0.x * q0.x + e0.y * q0.y + e0.z * q0.z + e0.w * q0.w
                + e1.x * q1.x + e1.y * q1.y + e1.z * q1.z + e1.w * q1.w;
#pragma unroll
        for (int o = 16; o; o >>= 1) s += __shfl_xor_sync(0xffffffffu, s, o);
        if (lane == 0) g_rinv[b * LC + l] = 1.f / s;
    }
#pragma unroll
    for (int j = 0; j < 4; j++) {
        cp[w][lane * 4 + j] = col[j];
        cp[w][128 + lane * 4 + j] = col[4 + j];
    }
    __syncthreads();
    int m = threadIdx.x;
    float c = cp[0][m] + cp[1][m] + cp[2][m] + cp[3][m]
            + cp[4][m] + cp[5][m] + cp[6][m] + cp[7][m];
    g_cpart[(b * 8 + rc) * 256 + m] = c;
}

__global__ void k_colfin(const float* __restrict__ qmask) {
    int b = blockIdx.x, m = threadIdx.x;
    const float* p = g_cpart + b * 8 * 256 + m;
    float c = p[0] + p[256] + p[512] + p[768] + p[1024] + p[1280] + p[1536] + p[1792];
    g_qcinv[b * LQ + m] = qmask[b * LQ + m] / c;
}

// ---------------- launch ----------------
extern "C" void kernel_launch(void* const* d_in, const int* in_sizes, int n_in,
                              void* d_out, int out_size) {
    const float* C     = (const float*)d_in[0];
    const float* Q     = (const float*)d_in[1];
    const float* cmask = (const float*)d_in[2];
    const float* qmask = (const float*)d_in[3];
    const float* w     = (const float*)d_in[4];
    float* out = (float*)d_out;

    float *pE, *pT, *pc1, *pq2, *prv, *pqc;
    cudaGetSymbolAddress((void**)&pE,   g_E);
    cudaGetSymbolAddress((void**)&pT,   g_T);
    cudaGetSymbolAddress((void**)&pc1,  g_c1);
    cudaGetSymbolAddress((void**)&pq2,  g_q2);
    cudaGetSymbolAddress((void**)&prv,  g_rinv);
    cudaGetSymbolAddress((void**)&pqc,  g_qcinv);

    // 1: bias vectors
    k_bias<<<dim3(5, B_), 256>>>(C, Q, w);

    // 2: G1  E = tf32(exp((C*w3)^T Q + c1 + q2))   [m=l (8 tiles), n=m' (4 tiles of 64), K=D]
    tgemm<true, true, true, false, true, true, 1><<<dim3(4, 8, B_), 128>>>(
        C, LC, (long)D_ * LC,  Q, LQ, (long)D_ * LQ,
        pE, LQ, (long)LC * LQ,  D_,
        w + 2 * D_, 0,  nullptr, 0,  pc1, pq2);

    // 3: sums -> rinv, col partials
    k_sums<<<dim3(8, B_), 256>>>(qmask, cmask);

    // 4 (profiled): G3  T_raw[m'][d] = sum_l E(l,m')*cm(l)*C(d,l)   [m=m' (2), n=d (2 of 64), K=Lc]
    // A = E (pre-rounded, no cvt); B = C with cmask kscale (cvt)
    tgemm<true, false, false, true, false, true, 0><<<dim3(2, 2, B_), 128>>>(
        pE, LQ, (long)LC * LQ,  C, LC, (long)D_ * LC,
        pT, D_, (long)LQ * D_,  LC,
        nullptr, 0,  cmask, LC,  nullptr, nullptr);

    // 5: qcinv[m'] = qm(m') / colsum(m')
    k_colfin<<<B_, 256>>>(qmask);

    // 6: fused G2+G4 + output assembly
    g24<<<dim3(LC / 64, 1, B_), 256>>>(
        Q, pT, pE, C, qmask, pqc, prv, out);
}

// round 13
// speedup vs baseline: 1.0579x; 1.0579x over previous
#include <cuda_runtime.h>
#include <cuda_bf16.h>
#include <cstdint>

#define B_  64
#define D_  128
#define LC  1024
#define LQ  256
#define FST 36       // fp32 smem row stride (144B: conflict-free STS.128 + ldmatrix)

// ---------------- scratch (static device arrays) ----------------
static __device__ float g_E   [(size_t)B_*LC*LQ];    // exp(S + biases), tf32-rounded
static __device__ float g_T   [(size_t)B_*LQ*D_];    // T_raw [m'][d] (unscaled)
static __device__ float g_rinv[B_*LC];
static __device__ float g_qcinv[B_*LQ];
static __device__ float g_cpart[B_*8*LQ];
static __device__ float g_c1[B_*LC];
static __device__ float g_q2[B_*LQ];

// ---------------- helpers ----------------
__device__ __forceinline__ uint32_t smem_u32(const void* p) {
    uint32_t a;
    asm("{ .reg .u64 t; cvta.to.shared.u64 t, %1; cvt.u32.u64 %0, t; }" : "=r"(a) : "l"(p));
    return a;
}

__device__ __forceinline__ float tf32r(float x) {
    uint32_t o; asm("cvt.rna.tf32.f32 %0, %1;" : "=r"(o) : "f"(x));
    return __uint_as_float(o);
}

#define LDSM_X4(r, a) \
    asm volatile("ldmatrix.sync.aligned.m8n8.x4.shared.b16 {%0,%1,%2,%3}, [%4];" \
        : "=r"((r)[0]), "=r"((r)[1]), "=r"((r)[2]), "=r"((r)[3]) : "r"(a))

#define MMA_TF32(c, a, b0, b1) \
    asm volatile("mma.sync.aligned.m16n8k8.row.col.f32.tf32.tf32.f32 " \
        "{%0,%1,%2,%3}, {%4,%5,%6,%7}, {%8,%9}, {%0,%1,%2,%3};" \
        : "+f"((c)[0]), "+f"((c)[1]), "+f"((c)[2]), "+f"((c)[3]) \
        : "r"((a)[0]), "r"((a)[1]), "r"((a)[2]), "r"((a)[3]), "r"(b0), "r"(b1))

template<bool CV>
__device__ __forceinline__ float4 cvt_sel(const float4& x) {
    if constexpr (!CV) return x;
    float4 t;
    t.x = tf32r(x.x); t.y = tf32r(x.y); t.z = tf32r(x.z); t.w = tf32r(x.w);
    return t;
}

// ---------------- operand loaders (256-thread CTA, 128-row tiles) ----------------
template<bool TRANS, bool KS>
__device__ __forceinline__ void ldg_op(const float* __restrict__ src, int ld, int mn0,
                                       int kk, const float* __restrict__ ks,
                                       int tid, float4 (&r)[4]) {
#pragma unroll
    for (int i = 0; i < 4; i++) {
        int v = i * 256 + tid;
        if constexpr (!TRANS) {
            int row = v >> 3, c4 = v & 7;
            float4 x = *reinterpret_cast<const float4*>(src + (size_t)(mn0 + row) * ld + kk + c4 * 4);
            if constexpr (KS) {
                float4 s = *reinterpret_cast<const float4*>(ks + kk + c4 * 4);
                x.x *= s.x; x.y *= s.y; x.z *= s.z; x.w *= s.w;
            }
            r[i] = x;
        } else {
            int mn = v & 127, krb = v >> 7;
            const float* p = src + (size_t)(kk + krb * 4) * ld + mn0 + mn;
            float4 x;
            x.x = p[0]; x.y = p[ld]; x.z = p[2 * (size_t)ld]; x.w = p[3 * (size_t)ld];
            if constexpr (KS) {
                const float* s = ks + kk + krb * 4;
                x.x *= s[0]; x.y *= s[1]; x.z *= s[2]; x.w *= s[3];
            }
            r[i] = x;
        }
    }
}

template<bool TRANS, bool CV>
__device__ __forceinline__ void sts_op(float4 (&r)[4], float* sm, int tid) {
#pragma unroll
    for (int i = 0; i < 4; i++) {
        int v = i * 256 + tid;
        int off;
        if constexpr (!TRANS) { int row = v >> 3, c4 = v & 7; off = row * FST + c4 * 4; }
        else                  { int mn = v & 127, krb = v >> 7; off = mn * FST + krb * 4; }
        *reinterpret_cast<float4*>(sm + off) = cvt_sel<CV>(r[i]);
    }
}

// ---------------- single-pass tf32 GEMM, double-buffered (compile-time buffer idx) ----------------
// EPI 0: plain fp32 ; EPI 1: tf32(exp(acc + biasR[row] + biasC[col]))
template<bool AT, bool BT, bool KSA, bool KSB, bool CVA, bool CVB, int EPI>
__global__ __launch_bounds__(256) void tgemm(
    const float* __restrict__ Ag, int lda, long batA,
    const float* __restrict__ Bg, int ldb, long batB,
    float* __restrict__ Cg, int ldc, long batC,
    int Kloc,
    const float* __restrict__ ksA, int ksAstr,
    const float* __restrict__ ksB, int ksBstr,
    const float* __restrict__ biasR, const float* __restrict__ biasC)
{
    extern __shared__ __align__(16) float sm[];
    const int TILE = 128 * FST;          // 4608 floats per tile
    float* sA0 = sm;           float* sA1 = sm + TILE;
    float* sB0 = sm + 2*TILE;  float* sB1 = sm + 3*TILE;

    const int zb = blockIdx.z;
    const int m0 = blockIdx.y << 7;
    const int n0 = blockIdx.x << 7;
    const float* Ab = Ag + (size_t)zb * batA;
    const float* Bb = Bg + (size_t)zb * batB;
    const float* kA = KSA ? (ksA + (size_t)zb * ksAstr) : nullptr;
    const float* kB = KSB ? (ksB + (size_t)zb * ksBstr) : nullptr;

    const int tid = threadIdx.x, wid = tid >> 5, lane = tid & 31;
    const int wm = (wid >> 2) * 64, wn = (wid & 3) * 32;

    float acc[4][4][4];
#pragma unroll
    for (int i = 0; i < 4; i++)
#pragma unroll
        for (int j = 0; j < 4; j++)
#pragma unroll
            for (int e = 0; e < 4; e++) acc[i][j][e] = 0.f;

    float4 ra[4], rb[4];
    const uint32_t a0 = smem_u32(sA0), a1 = smem_u32(sA1);
    const uint32_t b0 = smem_u32(sB0), b1 = smem_u32(sB1);
    const uint32_t lrow = (uint32_t)(lane & 15) * FST + ((lane >> 4) << 2);

    auto mmaph = [&](uint32_t bA, uint32_t bB) {
#pragma unroll
        for (int ks = 0; ks < 4; ks++) {
            uint32_t af[4][4];
#pragma unroll
            for (int mt = 0; mt < 4; mt++) {
                uint32_t aoff = ((uint32_t)(wm + mt * 16) * FST + lrow + ks * 8) * 4u;
                LDSM_X4(af[mt], bA + aoff);
            }
            uint32_t bf[2][4];
#pragma unroll
            for (int nb = 0; nb < 2; nb++) {
                uint32_t boff = ((uint32_t)(wn + nb * 16) * FST + lrow + ks * 8) * 4u;
                LDSM_X4(bf[nb], bB + boff);
            }
#pragma unroll
            for (int mt = 0; mt < 4; mt++)
#pragma unroll
                for (int nb = 0; nb < 2; nb++) {
                    MMA_TF32(acc[mt][nb * 2 + 0], af[mt], bf[nb][0], bf[nb][2]);
                    MMA_TF32(acc[mt][nb * 2 + 1], af[mt], bf[nb][1], bf[nb][3]);
                }
        }
    };
    auto ldg = [&](int kk) {
        ldg_op<AT, KSA>(Ab, lda, m0, kk, kA, tid, ra);
        ldg_op<BT, KSB>(Bb, ldb, n0, kk, kB, tid, rb);
    };
    auto sts = [&](float* dA, float* dB) {
        sts_op<AT, CVA>(ra, dA, tid);
        sts_op<BT, CVB>(rb, dB, tid);
    };

    const int nch = Kloc >> 5;           // even for all uses (4, 32, 8)
    ldg(0);
    sts(sA0, sB0);
    __syncthreads();

    for (int ch = 0; ch < nch; ch += 2) {
        if (ch + 1 < nch) ldg((ch + 1) << 5);
        mmaph(a0, b0);                                   // reads buf0
        if (ch + 1 < nch) {
            sts(sA1, sB1);                               // writes buf1 (last read pre-sync)
            __syncthreads();
            if (ch + 2 < nch) ldg((ch + 2) << 5);
            mmaph(a1, b1);                               // reads buf1
            if (ch + 2 < nch) {
                sts(sA0, sB0);                           // writes buf0
                __syncthreads();
            }
        }
    }

    float* Cb = Cg + (size_t)zb * batC;
#pragma unroll
    for (int mt = 0; mt < 4; mt++) {
        int r0 = m0 + wm + mt * 16 + (lane >> 2);
        int r1 = r0 + 8;
        float br0 = 0.f, br1 = 0.f;
        if constexpr (EPI == 1) { br0 = biasR[zb * LC + r0]; br1 = biasR[zb * LC + r1]; }
#pragma unroll
        for (int nt = 0; nt < 4; nt++) {
            int col = n0 + wn + nt * 8 + (lane & 3) * 2;
            float2 v0, v1;
            v0.x = acc[mt][nt][0]; v0.y = acc[mt][nt][1];
            v1.x = acc[mt][nt][2]; v1.y = acc[mt][nt][3];
            if constexpr (EPI == 1) {
                float bc0 = biasC[zb * LQ + col], bc1 = biasC[zb * LQ + col + 1];
                v0.x = tf32r(__expf(v0.x + br0 + bc0)); v0.y = tf32r(__expf(v0.y + br0 + bc1));
                v1.x = tf32r(__expf(v1.x + br1 + bc0)); v1.y = tf32r(__expf(v1.y + br1 + bc1));
            }
            *reinterpret_cast<float2*>(Cb + (size_t)r0 * ldc + col) = v0;
            *reinterpret_cast<float2*>(Cb + (size_t)r1 * ldc + col) = v1;
        }
    }
}

// ---------------- fused G2+G4 (double-buffered): A = [Q*qm ; T_raw*qcinv], B = E tile ----------------
__global__ __launch_bounds__(256) void g24(
    const float* __restrict__ Q, const float* __restrict__ T,
    const float* __restrict__ E, const float* __restrict__ C,
    const float* __restrict__ qmask, const float* __restrict__ qcinv,
    const float* __restrict__ rinv, float* __restrict__ out)
{
    extern __shared__ __align__(16) float sm[];
    const int PA = 256 * FST;    // 9216 floats
    const int PB = 64 * FST;     // 2304 floats
    float* sA0 = sm;                 float* sB0 = sm + PA;
    float* sA1 = sm + PA + PB;       float* sB1 = sm + 2 * PA + PB;

    const int zb = blockIdx.z;
    const int n0 = blockIdx.x * 64;
    const float* Qb = Q + (size_t)zb * D_ * LQ;
    const float* Tb = T + (size_t)zb * LQ * D_;
    const float* Eb = E + (size_t)zb * LC * LQ;
    const float* qm = qmask + zb * LQ;
    const float* qc = qcinv + zb * LQ;

    const int tid = threadIdx.x, wid = tid >> 5, lane = tid & 31;
    const int wm = (wid >> 1) * 64, wn = (wid & 1) * 32;

    float acc[4][4][4];
#pragma unroll
    for (int i = 0; i < 4; i++)
#pragma unroll
        for (int j = 0; j < 4; j++)
#pragma unroll
            for (int e = 0; e < 4; e++) acc[i][j][e] = 0.f;

    float4 ra[8], rb[2];

    auto ldg = [&](int kk) {
#pragma unroll
        for (int i = 0; i < 4; i++) {                 // Q half, rows 0..127, K-fast
            int v = i * 256 + tid;
            int row = v >> 3, c4 = v & 7;
            float4 x = *reinterpret_cast<const float4*>(Qb + (size_t)row * LQ + kk + c4 * 4);
            float4 s = *reinterpret_cast<const float4*>(qm + kk + c4 * 4);
            x.x *= s.x; x.y *= s.y; x.z *= s.z; x.w *= s.w;
            ra[i] = x;
        }
#pragma unroll
        for (int i = 0; i < 4; i++) {                 // T half, rows 128..255, K-slow
            int v = i * 256 + tid;
            int mn = v & 127, krb = v >> 7;
            const float* p = Tb + (size_t)(kk + krb * 4) * D_ + mn;
            const float* s = qc + kk + krb * 4;
            float4 x;
            x.x = p[0] * s[0]; x.y = p[D_] * s[1];
            x.z = p[2 * D_] * s[2]; x.w = p[3 * D_] * s[3];
            ra[4 + i] = x;
        }
#pragma unroll
        for (int i = 0; i < 2; i++) {                 // E tile, 64 rows (l), K-fast, pre-rounded
            int v = i * 256 + tid;
            int row = v >> 3, c4 = v & 7;
            rb[i] = *reinterpret_cast<const float4*>(Eb + (size_t)(n0 + row) * LQ + kk + c4 * 4);
        }
    };
    auto sts = [&](float* dA, float* dB) {
#pragma unroll
        for (int i = 0; i < 4; i++) {
            int v = i * 256 + tid;
            int row = v >> 3, c4 = v & 7;
            *reinterpret_cast<float4*>(dA + row * FST + c4 * 4) = cvt_sel<true>(ra[i]);
        }
#pragma unroll
        for (int i = 0; i < 4; i++) {
            int v = i * 256 + tid;
            int mn = v & 127, krb = v >> 7;
            *reinterpret_cast<float4*>(dA + (128 + mn) * FST + krb * 4) = cvt_sel<true>(ra[4 + i]);
        }
#pragma unroll
        for (int i = 0; i < 2; i++) {
            int v = i * 256 + tid;
            int row = v >> 3, c4 = v & 7;
            *reinterpret_cast<float4*>(dB + row * FST + c4 * 4) = rb[i];
        }
    };

    const uint32_t a0 = smem_u32(sA0), a1 = smem_u32(sA1);
    const uint32_t b0 = smem_u32(sB0), b1 = smem_u32(sB1);
    const uint32_t lrow = (uint32_t)(lane & 15) * FST + ((lane >> 4) << 2);

    auto mmaph = [&](uint32_t bA, uint32_t bB) {
#pragma unroll
        for (int ks = 0; ks < 4; ks++) {
            uint32_t af[4][4];
#pragma unroll
            for (int mt = 0; mt < 4; mt++) {
                uint32_t aoff = ((uint32_t)(wm + mt * 16) * FST + lrow + ks * 8) * 4u;
                LDSM_X4(af[mt], bA + aoff);
            }
            uint32_t bf[2][4];
#pragma unroll
            for (int nb = 0; nb < 2; nb++) {
                uint32_t boff = ((uint32_t)(wn + nb * 16) * FST + lrow + ks * 8) * 4u;
                LDSM_X4(bf[nb], bB + boff);
            }
#pragma unroll
            for (int mt = 0; mt < 4; mt++)
#pragma unroll
                for (int nb = 0; nb < 2; nb++) {
                    MMA_TF32(acc[mt][nb * 2 + 0], af[mt], bf[nb][0], bf[nb][2]);
                    MMA_TF32(acc[mt][nb * 2 + 1], af[mt], bf[nb][1], bf[nb][3]);
                }
        }
    };

    const int nch = LQ >> 5;   // 8
    ldg(0);
    sts(sA0, sB0);
    __syncthreads();

    for (int ch = 0; ch < nch; ch += 2) {
        if (ch + 1 < nch) ldg((ch + 1) << 5);
        mmaph(a0, b0);
        if (ch + 1 < nch) {
            sts(sA1, sB1);
            __syncthreads();
            if (ch + 2 < nch) ldg((ch + 2) << 5);
            mmaph(a1, b1);
            if (ch + 2 < nch) {
                sts(sA0, sB0);
                __syncthreads();
            }
        }
    }

    // epilogue: rows < 128 => At (channels 0,1,2); rows >= 128 => Bv (channel 3)
    const float* Cb = C + (size_t)zb * D_ * LC;
    const float* rv = rinv + zb * LC;
    float* O = out + (size_t)zb * 4 * D_ * LC;
#pragma unroll
    for (int mt = 0; mt < 4; mt++) {
        int r0 = wm + mt * 16 + (lane >> 2);
        int r1 = r0 + 8;
#pragma unroll
        for (int nt = 0; nt < 4; nt++) {
            int col = n0 + wn + nt * 8 + (lane & 3) * 2;
            float c0 = rv[col], c1v = rv[col + 1];
            float2 v0, v1;
            v0.x = acc[mt][nt][0] * c0; v0.y = acc[mt][nt][1] * c1v;
            v1.x = acc[mt][nt][2] * c0; v1.y = acc[mt][nt][3] * c1v;
            if (wm < 128) {
                int d0 = r0, d1 = r1;
                float2 cc0 = *reinterpret_cast<const float2*>(Cb + (size_t)d0 * LC + col);
                float2 cc1 = *reinterpret_cast<const float2*>(Cb + (size_t)d1 * LC + col);
                *reinterpret_cast<float2*>(O + (size_t)d0 * LC + col) = cc0;
                *reinterpret_cast<float2*>(O + (size_t)d1 * LC + col) = cc1;
                *reinterpret_cast<float2*>(O + (size_t)(D_ + d0) * LC + col) = v0;
                *reinterpret_cast<float2*>(O + (size_t)(D_ + d1) * LC + col) = v1;
                float2 m0v, m1v;
                m0v.x = cc0.x * v0.x; m0v.y = cc0.y * v0.y;
                m1v.x = cc1.x * v1.x; m1v.y = cc1.y * v1.y;
                *reinterpret_cast<float2*>(O + (size_t)(2 * D_ + d0) * LC + col) = m0v;
                *reinterpret_cast<float2*>(O + (size_t)(2 * D_ + d1) * LC + col) = m1v;
            } else {
                int d0 = r0 - 128, d1 = r1 - 128;
                float2 cc0 = *reinterpret_cast<const float2*>(Cb + (size_t)d0 * LC + col);
                float2 cc1 = *reinterpret_cast<const float2*>(Cb + (size_t)d1 * LC + col);
                float2 b0v, b1v;
                b0v.x = cc0.x * v0.x; b0v.y = cc0.y * v0.y;
                b1v.x = cc1.x * v1.x; b1v.y = cc1.y * v1.y;
                *reinterpret_cast<float2*>(O + (size_t)(3 * D_ + d0) * LC + col) = b0v;
                *reinterpret_cast<float2*>(O + (size_t)(3 * D_ + d1) * LC + col) = b1v;
            }
        }
    }
}

// ---------------- K1: bias vectors c1[l] = Ct.w1, q2[m] = Qt.w2 ----------------
__global__ void k_bias(const float* __restrict__ C, const float* __restrict__ Q,
                       const float* __restrict__ w) {
    int b = blockIdx.y, seg = blockIdx.x, t = threadIdx.x;
    if (seg < 4) {
        int l = seg * 256 + t;
        const float* Cb = C + (size_t)b * D_ * LC;
        float acc = 0.f;
#pragma unroll 8
        for (int d = 0; d < D_; d++) acc += Cb[(size_t)d * LC + l] * __ldg(w + d);
        g_c1[b * LC + l] = acc;
    } else {
        int m = t;
        const float* Qb = Q + (size_t)b * D_ * LQ;
        float acc = 0.f;
#pragma unroll 8
        for (int d = 0; d < D_; d++) acc += Qb[(size_t)d * LQ + m] * __ldg(w + D_ + d);
        g_q2[b * LQ + m] = acc;
    }
}

// ---------------- sums: rinv[l] = 1/sum_m E*qm, col partials for cinv ----------------
__global__ __launch_bounds__(256) void k_sums(const float* __restrict__ qmask,
                                              const float* __restrict__ cmask) {
    int b = blockIdx.y, rc = blockIdx.x;
    int w = threadIdx.x >> 5, lane = threadIdx.x & 31;
    __shared__ float cp[8][256];
    float4 q0 = *reinterpret_cast<const float4*>(qmask + b * LQ + lane * 4);
    float4 q1 = *reinterpret_cast<const float4*>(qmask + b * LQ + 128 + lane * 4);
    float col[8] = {0.f, 0.f, 0.f, 0.f, 0.f, 0.f, 0.f, 0.f};
#pragma unroll 4
    for (int rr = 0; rr < 16; rr++) {
        int l = rc * 128 + w * 16 + rr;
        const float* Er = g_E + ((size_t)b * LC + l) * LQ;
        float4 e0 = *reinterpret_cast<const float4*>(Er + lane * 4);
        float4 e1 = *reinterpret_cast<const float4*>(Er + 128 + lane * 4);
        float cm = cmask[b * LC + l];
        col[0] += e0.x * cm; col[1] += e0.y * cm; col[2] += e0.z * cm; col[3] += e0.w * cm;
        col[4] += e1.x * cm; col[5] += e1.y * cm; col[6] += e1.z * cm; col[7] += e1.w * cm;
        float s = e0.x * q0.x + e0.y * q0.y + e0.z * q0.z + e0.w * q0.w
                + e1.x * q1.x + e1.y * q1.y + e1.z * q1.z + e1.w * q1.w;
#pragma unroll
        for (int o = 16; o; o >>= 1) s += __shfl_xor_sync(0xffffffffu, s, o);
        if (lane == 0) g_rinv[b * LC + l] = 1.f / s;
    }
#pragma unroll
    for (int j = 0; j < 4; j++) {
        cp[w][lane * 4 + j] = col[j];
        cp[w][128 + lane * 4 + j] = col[4 + j];
    }
    __syncthreads();
    int m = threadIdx.x;
    float c = cp[0][m] + cp[1][m] + cp[2][m] + cp[3][m]
            + cp[4][m] + cp[5][m] + cp[6][m] + cp[7][m];
    g_cpart[(b * 8 + rc) * 256 + m] = c;
}

__global__ void k_colfin(const float* __restrict__ qmask) {
    int b = blockIdx.x, m = threadIdx.x;
    const float* p = g_cpart + b * 8 * 256 + m;
    float c = p[0] + p[256] + p[512] + p[768] + p[1024] + p[1280] + p[1536] + p[1792];
    g_qcinv[b * LQ + m] = qmask[b * LQ + m] / c;
}

// ---------------- launch ----------------
extern "C" void kernel_launch(void* const* d_in, const int* in_sizes, int n_in,
                              void* d_out, int out_size) {
    const float* C     = (const float*)d_in[0];
    const float* Q     = (const float*)d_in[1];
    const float* cmask = (const float*)d_in[2];
    const float* qmask = (const float*)d_in[3];
    const float* w     = (const float*)d_in[4];
    float* out = (float*)d_out;

    float *pE, *pT, *pc1, *pq2, *prv, *pqc;
    cudaGetSymbolAddress((void**)&pE,   g_E);
    cudaGetSymbolAddress((void**)&pT,   g_T);
    cudaGetSymbolAddress((void**)&pc1,  g_c1);
    cudaGetSymbolAddress((void**)&pq2,  g_q2);
    cudaGetSymbolAddress((void**)&prv,  g_rinv);
    cudaGetSymbolAddress((void**)&pqc,  g_qcinv);

    const int TG_SMEM  = 4 * 128 * FST * 4;                    // 73728 B
    const int G24_SMEM = 2 * (256 + 64) * FST * 4;             // 92160 B
    static int smem_set = 0;
    if (!smem_set) {
        cudaFuncSetAttribute(tgemm<true, true,  true,  false, true, true, 1>,
                             cudaFuncAttributeMaxDynamicSharedMemorySize, TG_SMEM);
        cudaFuncSetAttribute(tgemm<true, false, false, true,  false, true, 0>,
                             cudaFuncAttributeMaxDynamicSharedMemorySize, TG_SMEM);
        cudaFuncSetAttribute(g24, cudaFuncAttributeMaxDynamicSharedMemorySize, G24_SMEM);
        smem_set = 1;
    }

    // 1: bias vectors
    k_bias<<<dim3(5, B_), 256>>>(C, Q, w);

    // 2: G1  E = tf32(exp((C*w3)^T Q + c1 + q2))   [m=l (8 tiles), n=m' (2), K=D]
    tgemm<true, true, true, false, true, true, 1><<<dim3(2, 8, B_), 256, TG_SMEM>>>(
        C, LC, (long)D_ * LC,  Q, LQ, (long)D_ * LQ,
        pE, LQ, (long)LC * LQ,  D_,
        w + 2 * D_, 0,  nullptr, 0,  pc1, pq2);

    // 3: sums -> rinv, col partials
    k_sums<<<dim3(8, B_), 256>>>(qmask, cmask);

    // 4 (profiled): G3  T_raw[m'][d] = sum_l E(l,m')*cm(l)*C(d,l)   [m=m' (2), n=d (1), K=Lc]
    // A = E (pre-rounded, no cvt); B = C with cmask kscale (cvt)
    tgemm<true, false, false, true, false, true, 0><<<dim3(1, 2, B_), 256, TG_SMEM>>>(
        pE, LQ, (long)LC * LQ,  C, LC, (long)D_ * LC,
        pT, D_, (long)LQ * D_,  LC,
        nullptr, 0,  cmask, LC,  nullptr, nullptr);

    // 5: qcinv[m'] = qm(m') / colsum(m')
    k_colfin<<<B_, 256>>>(qmask);

    // 6: fused G2+G4 + output assembly
    g24<<<dim3(LC / 64, 1, B_), 256, G24_SMEM>>>(
        Q, pT, pE, C, qmask, pqc, prv, out);
}

// round 14
// speedup vs baseline: 1.1219x; 1.0605x over previous
#include <cuda_runtime.h>
#include <cuda_bf16.h>
#include <cstdint>

#define B_  64
#define D_  128
#define LC  1024
#define LQ  256
#define FST 36       // fp32 smem row stride (144B: conflict-free STS.128 + ldmatrix)

// ---------------- scratch (static device arrays) ----------------
static __device__ float g_E   [(size_t)B_*LC*LQ];    // exp(S + biases), tf32-rounded
static __device__ float g_T   [(size_t)B_*LQ*D_];    // T_raw [m'][d] (unscaled)
static __device__ float g_rp  [(size_t)B_*2*LC];     // rowsum partials (per x-tile)
static __device__ float g_cp  [(size_t)B_*8*LQ];     // colsum partials (per y-tile)
static __device__ float g_rinv[B_*LC];
static __device__ float g_qcinv[B_*LQ];
static __device__ float g_c1[B_*LC];
static __device__ float g_q2[B_*LQ];

// ---------------- helpers ----------------
__device__ __forceinline__ uint32_t smem_u32(const void* p) {
    uint32_t a;
    asm("{ .reg .u64 t; cvta.to.shared.u64 t, %1; cvt.u32.u64 %0, t; }" : "=r"(a) : "l"(p));
    return a;
}

__device__ __forceinline__ float tf32r(float x) {
    uint32_t o; asm("cvt.rna.tf32.f32 %0, %1;" : "=r"(o) : "f"(x));
    return __uint_as_float(o);
}

#define LDSM_X4(r, a) \
    asm volatile("ldmatrix.sync.aligned.m8n8.x4.shared.b16 {%0,%1,%2,%3}, [%4];" \
        : "=r"((r)[0]), "=r"((r)[1]), "=r"((r)[2]), "=r"((r)[3]) : "r"(a))

#define MMA_TF32(c, a, b0, b1) \
    asm volatile("mma.sync.aligned.m16n8k8.row.col.f32.tf32.tf32.f32 " \
        "{%0,%1,%2,%3}, {%4,%5,%6,%7}, {%8,%9}, {%0,%1,%2,%3};" \
        : "+f"((c)[0]), "+f"((c)[1]), "+f"((c)[2]), "+f"((c)[3]) \
        : "r"((a)[0]), "r"((a)[1]), "r"((a)[2]), "r"((a)[3]), "r"(b0), "r"(b1))

template<bool CV>
__device__ __forceinline__ float4 cvt_sel(const float4& x) {
    if constexpr (!CV) return x;
    float4 t;
    t.x = tf32r(x.x); t.y = tf32r(x.y); t.z = tf32r(x.z); t.w = tf32r(x.w);
    return t;
}

// ---------------- operand loaders (256-thread CTA, 128-row tiles) ----------------
template<bool TRANS, bool KS>
__device__ __forceinline__ void ldg_op(const float* __restrict__ src, int ld, int mn0,
                                       int kk, const float* __restrict__ ks,
                                       int tid, float4 (&r)[4]) {
#pragma unroll
    for (int i = 0; i < 4; i++) {
        int v = i * 256 + tid;
        if constexpr (!TRANS) {
            int row = v >> 3, c4 = v & 7;
            float4 x = *reinterpret_cast<const float4*>(src + (size_t)(mn0 + row) * ld + kk + c4 * 4);
            if constexpr (KS) {
                float4 s = *reinterpret_cast<const float4*>(ks + kk + c4 * 4);
                x.x *= s.x; x.y *= s.y; x.z *= s.z; x.w *= s.w;
            }
            r[i] = x;
        } else {
            int mn = v & 127, krb = v >> 7;
            const float* p = src + (size_t)(kk + krb * 4) * ld + mn0 + mn;
            float4 x;
            x.x = p[0]; x.y = p[ld]; x.z = p[2 * (size_t)ld]; x.w = p[3 * (size_t)ld];
            if constexpr (KS) {
                const float* s = ks + kk + krb * 4;
                x.x *= s[0]; x.y *= s[1]; x.z *= s[2]; x.w *= s[3];
            }
            r[i] = x;
        }
    }
}

template<bool TRANS, bool CV>
__device__ __forceinline__ void sts_op(float4 (&r)[4], float* sm, int tid) {
#pragma unroll
    for (int i = 0; i < 4; i++) {
        int v = i * 256 + tid;
        int off;
        if constexpr (!TRANS) { int row = v >> 3, c4 = v & 7; off = row * FST + c4 * 4; }
        else                  { int mn = v & 127, krb = v >> 7; off = mn * FST + krb * 4; }
        *reinterpret_cast<float4*>(sm + off) = cvt_sel<CV>(r[i]);
    }
}

// ---------------- single-pass tf32 GEMM (single-buffer, static smem) ----------------
// EPI 0: plain fp32 store
// EPI 1: E = tf32(exp(acc + c1[row] + q2[col])) store, + fused row/col sum partials
template<bool AT, bool BT, bool KSA, bool KSB, bool CVA, bool CVB, int EPI>
__global__ __launch_bounds__(256) void tgemm(
    const float* __restrict__ Ag, int lda, long batA,
    const float* __restrict__ Bg, int ldb, long batB,
    float* __restrict__ Cg, int ldc, long batC,
    int Kloc,
    const float* __restrict__ ksA, int ksAstr,
    const float* __restrict__ ksB, int ksBstr,
    const float* __restrict__ biasR, const float* __restrict__ biasC,
    const float* __restrict__ rowmask, const float* __restrict__ colmask,
    float* __restrict__ rp, float* __restrict__ cp)
{
    __shared__ __align__(16) float sA[128 * FST];
    __shared__ __align__(16) float sB[128 * FST];

    const int zb = blockIdx.z;
    const int m0 = blockIdx.y << 7;
    const int n0 = blockIdx.x << 7;
    const float* Ab = Ag + (size_t)zb * batA;
    const float* Bb = Bg + (size_t)zb * batB;
    const float* kA = KSA ? (ksA + (size_t)zb * ksAstr) : nullptr;
    const float* kB = KSB ? (ksB + (size_t)zb * ksBstr) : nullptr;

    const int tid = threadIdx.x, wid = tid >> 5, lane = tid & 31;
    const int wm = (wid >> 2) * 64, wn = (wid & 3) * 32;

    float acc[4][4][4];
#pragma unroll
    for (int i = 0; i < 4; i++)
#pragma unroll
        for (int j = 0; j < 4; j++)
#pragma unroll
            for (int e = 0; e < 4; e++) acc[i][j][e] = 0.f;

    float4 ra[4], rb[4];
    const uint32_t bA = smem_u32(sA), bB = smem_u32(sB);
    const uint32_t lrow = (uint32_t)(lane & 15) * FST + ((lane >> 4) << 2);

    const int nch = Kloc >> 5;
    ldg_op<AT, KSA>(Ab, lda, m0, 0, kA, tid, ra);
    ldg_op<BT, KSB>(Bb, ldb, n0, 0, kB, tid, rb);

    for (int ch = 0; ch < nch; ch++) {
        sts_op<AT, CVA>(ra, sA, tid);
        sts_op<BT, CVB>(rb, sB, tid);
        __syncthreads();
        if (ch + 1 < nch) {
            int kk = (ch + 1) << 5;
            ldg_op<AT, KSA>(Ab, lda, m0, kk, kA, tid, ra);
            ldg_op<BT, KSB>(Bb, ldb, n0, kk, kB, tid, rb);
        }
#pragma unroll
        for (int ks = 0; ks < 4; ks++) {
            uint32_t af[4][4];
#pragma unroll
            for (int mt = 0; mt < 4; mt++) {
                uint32_t aoff = ((uint32_t)(wm + mt * 16) * FST + lrow + ks * 8) * 4u;
                LDSM_X4(af[mt], bA + aoff);
            }
            uint32_t bf[2][4];
#pragma unroll
            for (int nb = 0; nb < 2; nb++) {
                uint32_t boff = ((uint32_t)(wn + nb * 16) * FST + lrow + ks * 8) * 4u;
                LDSM_X4(bf[nb], bB + boff);
            }
#pragma unroll
            for (int mt = 0; mt < 4; mt++)
#pragma unroll
                for (int nb = 0; nb < 2; nb++) {
                    MMA_TF32(acc[mt][nb * 2 + 0], af[mt], bf[nb][0], bf[nb][2]);
                    MMA_TF32(acc[mt][nb * 2 + 1], af[mt], bf[nb][1], bf[nb][3]);
                }
        }
        __syncthreads();
    }

    float* Cb = Cg + (size_t)zb * batC;

    if constexpr (EPI == 0) {
#pragma unroll
        for (int mt = 0; mt < 4; mt++) {
            int r0 = m0 + wm + mt * 16 + (lane >> 2);
            int r1 = r0 + 8;
#pragma unroll
            for (int nt = 0; nt < 4; nt++) {
                int col = n0 + wn + nt * 8 + (lane & 3) * 2;
                float2 v0, v1;
                v0.x = acc[mt][nt][0]; v0.y = acc[mt][nt][1];
                v1.x = acc[mt][nt][2]; v1.y = acc[mt][nt][3];
                *reinterpret_cast<float2*>(Cb + (size_t)r0 * ldc + col) = v0;
                *reinterpret_cast<float2*>(Cb + (size_t)r1 * ldc + col) = v1;
            }
        }
    } else {
        // EPI 1: exp epilogue + fused row/col sum partials
        __shared__ float srow[128][4];
        __shared__ float scol[128][2];
        float cs[8];
#pragma unroll
        for (int j = 0; j < 8; j++) cs[j] = 0.f;

#pragma unroll
        for (int mt = 0; mt < 4; mt++) {
            int rl0 = wm + mt * 16 + (lane >> 2);
            int r0 = m0 + rl0, r1 = r0 + 8;
            float br0 = biasR[zb * LC + r0], br1 = biasR[zb * LC + r1];
            float cm0 = rowmask[zb * LC + r0], cm1 = rowmask[zb * LC + r1];
            float rs0 = 0.f, rs1 = 0.f;
#pragma unroll
            for (int nt = 0; nt < 4; nt++) {
                int col = n0 + wn + nt * 8 + (lane & 3) * 2;
                float bc0 = biasC[zb * LQ + col], bc1 = biasC[zb * LQ + col + 1];
                float2 v0, v1;
                v0.x = tf32r(__expf(acc[mt][nt][0] + br0 + bc0));
                v0.y = tf32r(__expf(acc[mt][nt][1] + br0 + bc1));
                v1.x = tf32r(__expf(acc[mt][nt][2] + br1 + bc0));
                v1.y = tf32r(__expf(acc[mt][nt][3] + br1 + bc1));
                *reinterpret_cast<float2*>(Cb + (size_t)r0 * ldc + col) = v0;
                *reinterpret_cast<float2*>(Cb + (size_t)r1 * ldc + col) = v1;
                float qa = colmask[zb * LQ + col], qb = colmask[zb * LQ + col + 1];
                rs0 += v0.x * qa + v0.y * qb;
                rs1 += v1.x * qa + v1.y * qb;
                cs[nt * 2 + 0] += v0.x * cm0 + v1.x * cm1;
                cs[nt * 2 + 1] += v0.y * cm0 + v1.y * cm1;
            }
            // reduce rowsums over the 4 lanes sharing each row (lane&3)
            rs0 += __shfl_xor_sync(0xffffffffu, rs0, 1);
            rs0 += __shfl_xor_sync(0xffffffffu, rs0, 2);
            rs1 += __shfl_xor_sync(0xffffffffu, rs1, 1);
            rs1 += __shfl_xor_sync(0xffffffffu, rs1, 2);
            if ((lane & 3) == 0) {
                srow[rl0][wid & 3] = rs0;
                srow[rl0 + 8][wid & 3] = rs1;
            }
        }
        // reduce colsums over the 8 lane-groups sharing each col (lane>>2)
#pragma unroll
        for (int j = 0; j < 8; j++) {
            cs[j] += __shfl_xor_sync(0xffffffffu, cs[j], 4);
            cs[j] += __shfl_xor_sync(0xffffffffu, cs[j], 8);
            cs[j] += __shfl_xor_sync(0xffffffffu, cs[j], 16);
        }
        if (lane < 4) {
#pragma unroll
            for (int nt = 0; nt < 4; nt++) {
#pragma unroll
                for (int e = 0; e < 2; e++) {
                    int cl = wn + nt * 8 + lane * 2 + e;
                    scol[cl][wid >> 2] = cs[nt * 2 + e];
                }
            }
        }
        __syncthreads();
        if (tid < 128) {
            float r = srow[tid][0] + srow[tid][1] + srow[tid][2] + srow[tid][3];
            rp[((size_t)zb * 2 + blockIdx.x) * LC + m0 + tid] = r;
            float c = scol[tid][0] + scol[tid][1];
            cp[((size_t)zb * 8 + blockIdx.y) * LQ + n0 + tid] = c;
        }
    }
}

// ---------------- fused G2+G4: stacked A = [Q*qm ; T_raw*qcinv], B = E tile ----------------
__global__ __launch_bounds__(256) void g24(
    const float* __restrict__ Q, const float* __restrict__ T,
    const float* __restrict__ E, const float* __restrict__ C,
    const float* __restrict__ qmask, const float* __restrict__ qcinv,
    const float* __restrict__ rinv, float* __restrict__ out)
{
    __shared__ __align__(16) float sA[256 * FST];
    __shared__ __align__(16) float sB[64 * FST];

    const int zb = blockIdx.z;
    const int n0 = blockIdx.x * 64;
    const float* Qb = Q + (size_t)zb * D_ * LQ;
    const float* Tb = T + (size_t)zb * LQ * D_;
    const float* Eb = E + (size_t)zb * LC * LQ;
    const float* qm = qmask + zb * LQ;
    const float* qc = qcinv + zb * LQ;

    const int tid = threadIdx.x, wid = tid >> 5, lane = tid & 31;
    const int wm = (wid >> 1) * 64, wn = (wid & 1) * 32;

    float acc[4][4][4];
#pragma unroll
    for (int i = 0; i < 4; i++)
#pragma unroll
        for (int j = 0; j < 4; j++)
#pragma unroll
            for (int e = 0; e < 4; e++) acc[i][j][e] = 0.f;

    float4 ra[8], rb[2];

    auto ldgA = [&](int kk) {
#pragma unroll
        for (int i = 0; i < 4; i++) {                 // Q half, rows 0..127, K-fast
            int v = i * 256 + tid;
            int row = v >> 3, c4 = v & 7;
            float4 x = *reinterpret_cast<const float4*>(Qb + (size_t)row * LQ + kk + c4 * 4);
            float4 s = *reinterpret_cast<const float4*>(qm + kk + c4 * 4);
            x.x *= s.x; x.y *= s.y; x.z *= s.z; x.w *= s.w;
            ra[i] = x;
        }
#pragma unroll
        for (int i = 0; i < 4; i++) {                 // T half, rows 128..255, K-slow
            int v = i * 256 + tid;
            int mn = v & 127, krb = v >> 7;
            const float* p = Tb + (size_t)(kk + krb * 4) * D_ + mn;
            const float* s = qc + kk + krb * 4;
            float4 x;
            x.x = p[0] * s[0]; x.y = p[D_] * s[1];
            x.z = p[2 * D_] * s[2]; x.w = p[3 * D_] * s[3];
            ra[4 + i] = x;
        }
    };
    auto ldgB = [&](int kk) {
#pragma unroll
        for (int i = 0; i < 2; i++) {                 // E tile, 64 rows (l), pre-rounded
            int v = i * 256 + tid;
            int row = v >> 3, c4 = v & 7;
            rb[i] = *reinterpret_cast<const float4*>(Eb + (size_t)(n0 + row) * LQ + kk + c4 * 4);
        }
    };
    auto sts = [&]() {
#pragma unroll
        for (int i = 0; i < 4; i++) {
            int v = i * 256 + tid;
            int row = v >> 3, c4 = v & 7;
            *reinterpret_cast<float4*>(sA + row * FST + c4 * 4) = cvt_sel<true>(ra[i]);
        }
#pragma unroll
        for (int i = 0; i < 4; i++) {
            int v = i * 256 + tid;
            int mn = v & 127, krb = v >> 7;
            *reinterpret_cast<float4*>(sA + (128 + mn) * FST + krb * 4) = cvt_sel<true>(ra[4 + i]);
        }
#pragma unroll
        for (int i = 0; i < 2; i++) {
            int v = i * 256 + tid;
            int row = v >> 3, c4 = v & 7;
            *reinterpret_cast<float4*>(sB + row * FST + c4 * 4) = rb[i];
        }
    };

    const uint32_t bA = smem_u32(sA), bB = smem_u32(sB);
    const uint32_t lrow = (uint32_t)(lane & 15) * FST + ((lane >> 4) << 2);

    const int nch = LQ >> 5;   // 8
    ldgA(0); ldgB(0);

    for (int ch = 0; ch < nch; ch++) {
        sts();
        __syncthreads();
        if (ch + 1 < nch) { ldgA((ch + 1) << 5); ldgB((ch + 1) << 5); }
#pragma unroll
        for (int ks = 0; ks < 4; ks++) {
            uint32_t af[4][4];
#pragma unroll
            for (int mt = 0; mt < 4; mt++) {
                uint32_t aoff = ((uint32_t)(wm + mt * 16) * FST + lrow + ks * 8) * 4u;
                LDSM_X4(af[mt], bA + aoff);
            }
            uint32_t bf[2][4];
#pragma unroll
            for (int nb = 0; nb < 2; nb++) {
                uint32_t boff = ((uint32_t)(wn + nb * 16) * FST + lrow + ks * 8) * 4u;
                LDSM_X4(bf[nb], bB + boff);
            }
#pragma unroll
            for (int mt = 0; mt < 4; mt++)
#pragma unroll
                for (int nb = 0; nb < 2; nb++) {
                    MMA_TF32(acc[mt][nb * 2 + 0], af[mt], bf[nb][0], bf[nb][2]);
                    MMA_TF32(acc[mt][nb * 2 + 1], af[mt], bf[nb][1], bf[nb][3]);
                }
        }
        __syncthreads();
    }

    // epilogue: rows < 128 => At (channels 0,1,2); rows >= 128 => Bv (channel 3)
    const float* Cb = C + (size_t)zb * D_ * LC;
    const float* rv = rinv + zb * LC;
    float* O = out + (size_t)zb * 4 * D_ * LC;
#pragma unroll
    for (int mt = 0; mt < 4; mt++) {
        int r0 = wm + mt * 16 + (lane >> 2);
        int r1 = r0 + 8;
#pragma unroll
        for (int nt = 0; nt < 4; nt++) {
            int col = n0 + wn + nt * 8 + (lane & 3) * 2;
            float c0 = rv[col], c1v = rv[col + 1];
            float2 v0, v1;
            v0.x = acc[mt][nt][0] * c0; v0.y = acc[mt][nt][1] * c1v;
            v1.x = acc[mt][nt][2] * c0; v1.y = acc[mt][nt][3] * c1v;
            if (wm < 128) {
                int d0 = r0, d1 = r1;
                float2 cc0 = *reinterpret_cast<const float2*>(Cb + (size_t)d0 * LC + col);
                float2 cc1 = *reinterpret_cast<const float2*>(Cb + (size_t)d1 * LC + col);
                *reinterpret_cast<float2*>(O + (size_t)d0 * LC + col) = cc0;
                *reinterpret_cast<float2*>(O + (size_t)d1 * LC + col) = cc1;
                *reinterpret_cast<float2*>(O + (size_t)(D_ + d0) * LC + col) = v0;
                *reinterpret_cast<float2*>(O + (size_t)(D_ + d1) * LC + col) = v1;
                float2 m0v, m1v;
                m0v.x = cc0.x * v0.x; m0v.y = cc0.y * v0.y;
                m1v.x = cc1.x * v1.x; m1v.y = cc1.y * v1.y;
                *reinterpret_cast<float2*>(O + (size_t)(2 * D_ + d0) * LC + col) = m0v;
                *reinterpret_cast<float2*>(O + (size_t)(2 * D_ + d1) * LC + col) = m1v;
            } else {
                int d0 = r0 - 128, d1 = r1 - 128;
                float2 cc0 = *reinterpret_cast<const float2*>(Cb + (size_t)d0 * LC + col);
                float2 cc1 = *reinterpret_cast<const float2*>(Cb + (size_t)d1 * LC + col);
                float2 b0v, b1v;
                b0v.x = cc0.x * v0.x; b0v.y = cc0.y * v0.y;
                b1v.x = cc1.x * v1.x; b1v.y = cc1.y * v1.y;
                *reinterpret_cast<float2*>(O + (size_t)(3 * D_ + d0) * LC + col) = b0v;
                *reinterpret_cast<float2*>(O + (size_t)(3 * D_ + d1) * LC + col) = b1v;
            }
        }
    }
}

// ---------------- K1: bias vectors c1[l] = Ct.w1, q2[m] = Qt.w2 ----------------
__global__ void k_bias(const float* __restrict__ C, const float* __restrict__ Q,
                       const float* __restrict__ w) {
    int b = blockIdx.y, seg = blockIdx.x, t = threadIdx.x;
    if (seg < 4) {
        int l = seg * 256 + t;
        const float* Cb = C + (size_t)b * D_ * LC;
        float acc = 0.f;
#pragma unroll 8
        for (int d = 0; d < D_; d++) acc += Cb[(size_t)d * LC + l] * __ldg(w + d);
        g_c1[b * LC + l] = acc;
    } else {
        int m = t;
        const float* Qb = Q + (size_t)b * D_ * LQ;
        float acc = 0.f;
#pragma unroll 8
        for (int d = 0; d < D_; d++) acc += Qb[(size_t)d * LQ + m] * __ldg(w + D_ + d);
        g_q2[b * LQ + m] = acc;
    }
}

// ---------------- finish: rinv from row partials, qcinv from col partials ----------------
__global__ void k_finish(const float* __restrict__ qmask) {
    int b = blockIdx.x;
    for (int l = threadIdx.x; l < LC; l += 256) {
        float s = g_rp[((size_t)b * 2 + 0) * LC + l] + g_rp[((size_t)b * 2 + 1) * LC + l];
        g_rinv[b * LC + l] = 1.f / s;
    }
    int m = threadIdx.x;
    float c = 0.f;
#pragma unroll
    for (int y = 0; y < 8; y++) c += g_cp[((size_t)b * 8 + y) * LQ + m];
    g_qcinv[b * LQ + m] = qmask[b * LQ + m] / c;
}

// ---------------- launch ----------------
extern "C" void kernel_launch(void* const* d_in, const int* in_sizes, int n_in,
                              void* d_out, int out_size) {
    const float* C     = (const float*)d_in[0];
    const float* Q     = (const float*)d_in[1];
    const float* cmask = (const float*)d_in[2];
    const float* qmask = (const float*)d_in[3];
    const float* w     = (const float*)d_in[4];
    float* out = (float*)d_out;

    float *pE, *pT, *pc1, *pq2, *prv, *pqc, *prp, *pcp;
    cudaGetSymbolAddress((void**)&pE,   g_E);
    cudaGetSymbolAddress((void**)&pT,   g_T);
    cudaGetSymbolAddress((void**)&pc1,  g_c1);
    cudaGetSymbolAddress((void**)&pq2,  g_q2);
    cudaGetSymbolAddress((void**)&prv,  g_rinv);
    cudaGetSymbolAddress((void**)&pqc,  g_qcinv);
    cudaGetSymbolAddress((void**)&prp,  g_rp);
    cudaGetSymbolAddress((void**)&pcp,  g_cp);

    // 1: bias vectors
    k_bias<<<dim3(5, B_), 256>>>(C, Q, w);

    // 2: G1  E = tf32(exp((C*w3)^T Q + c1 + q2)) + fused row/col sum partials
    tgemm<true, true, true, false, true, true, 1><<<dim3(2, 8, B_), 256>>>(
        C, LC, (long)D_ * LC,  Q, LQ, (long)D_ * LQ,
        pE, LQ, (long)LC * LQ,  D_,
        w + 2 * D_, 0,  nullptr, 0,  pc1, pq2,
        cmask, qmask, prp, pcp);

    // 3: finish sums -> rinv, qcinv
    k_finish<<<B_, 256>>>(qmask);

    // 4 (profiled): G3  T_raw[m'][d] = sum_l E(l,m')*cm(l)*C(d,l)   [m=m' (2), n=d (1), K=Lc]
    tgemm<true, false, false, true, false, true, 0><<<dim3(1, 2, B_), 256>>>(
        pE, LQ, (long)LC * LQ,  C, LC, (long)D_ * LC,
        pT, D_, (long)LQ * D_,  LC,
        nullptr, 0,  cmask, LC,  nullptr, nullptr,
        nullptr, nullptr, nullptr, nullptr);

    // 5: fused G2+G4 + output assembly
    g24<<<dim3(LC / 64, 1, B_), 256>>>(
        Q, pT, pE, C, qmask, pqc, prv, out);
}

// round 15
// speedup vs baseline: 1.1722x; 1.0448x over previous
#include <cuda_runtime.h>
#include <cuda_bf16.h>
#include <cstdint>

#define B_  64
#define D_  128
#define LC  1024
#define LQ  256
#define FST 36       // fp32 smem row stride (144B: conflict-free STS.128 + ldmatrix)

// ---------------- scratch (static device arrays) ----------------
static __device__ float g_E [(size_t)B_*LC*LQ];    // exp(S + biases), tf32-rounded
static __device__ float g_T [(size_t)B_*LQ*D_];    // T_raw [m'][d] (unscaled)
static __device__ float g_rp[(size_t)B_*2*LC];     // rowsum partials (per x-tile)
static __device__ float g_cp[(size_t)B_*8*LQ];     // colsum partials (per y-tile)

// ---------------- helpers ----------------
__device__ __forceinline__ uint32_t smem_u32(const void* p) {
    uint32_t a;
    asm("{ .reg .u64 t; cvta.to.shared.u64 t, %1; cvt.u32.u64 %0, t; }" : "=r"(a) : "l"(p));
    return a;
}

__device__ __forceinline__ float tf32r(float x) {
    uint32_t o; asm("cvt.rna.tf32.f32 %0, %1;" : "=r"(o) : "f"(x));
    return __uint_as_float(o);
}

#define LDSM_X4(r, a) \
    asm volatile("ldmatrix.sync.aligned.m8n8.x4.shared.b16 {%0,%1,%2,%3}, [%4];" \
        : "=r"((r)[0]), "=r"((r)[1]), "=r"((r)[2]), "=r"((r)[3]) : "r"(a))

#define MMA_TF32(c, a, b0, b1) \
    asm volatile("mma.sync.aligned.m16n8k8.row.col.f32.tf32.tf32.f32 " \
        "{%0,%1,%2,%3}, {%4,%5,%6,%7}, {%8,%9}, {%0,%1,%2,%3};" \
        : "+f"((c)[0]), "+f"((c)[1]), "+f"((c)[2]), "+f"((c)[3]) \
        : "r"((a)[0]), "r"((a)[1]), "r"((a)[2]), "r"((a)[3]), "r"(b0), "r"(b1))

template<bool CV>
__device__ __forceinline__ float4 cvt_sel(const float4& x) {
    if constexpr (!CV) return x;
    float4 t;
    t.x = tf32r(x.x); t.y = tf32r(x.y); t.z = tf32r(x.z); t.w = tf32r(x.w);
    return t;
}

// ---------------- shared MMA phase (128xN A x 128-col B tiles in smem) ----------------
#define MMA_PHASE(bA, bB) \
    do { \
        _Pragma("unroll") \
        for (int ks = 0; ks < 4; ks++) { \
            uint32_t af[4][4]; \
            _Pragma("unroll") \
            for (int mt = 0; mt < 4; mt++) { \
                uint32_t aoff = ((uint32_t)(wm + mt * 16) * FST + lrow + ks * 8) * 4u; \
                LDSM_X4(af[mt], (bA) + aoff); \
            } \
            uint32_t bf[2][4]; \
            _Pragma("unroll") \
            for (int nb = 0; nb < 2; nb++) { \
                uint32_t boff = ((uint32_t)(wn + nb * 16) * FST + lrow + ks * 8) * 4u; \
                LDSM_X4(bf[nb], (bB) + boff); \
            } \
            _Pragma("unroll") \
            for (int mt = 0; mt < 4; mt++) \
                _Pragma("unroll") \
                for (int nb = 0; nb < 2; nb++) { \
                    MMA_TF32(acc[mt][nb * 2 + 0], af[mt], bf[nb][0], bf[nb][2]); \
                    MMA_TF32(acc[mt][nb * 2 + 1], af[mt], bf[nb][1], bf[nb][3]); \
                } \
        } \
    } while (0)

// ---------------- G1: E = tf32(exp((C*w3)^T Q + c1 + q2)), fused bias + sum partials ----------------
__global__ __launch_bounds__(256) void g1(
    const float* __restrict__ C, const float* __restrict__ Q,
    const float* __restrict__ w,
    const float* __restrict__ cmask, const float* __restrict__ qmask,
    float* __restrict__ E, float* __restrict__ rp, float* __restrict__ cp)
{
    __shared__ __align__(16) float sA[128 * FST];
    __shared__ __align__(16) float sB[128 * FST];
    __shared__ float sbias[4][128];      // [0,1]: c1 halves; [2,3]: q2 halves
    __shared__ float srow[128][4];
    __shared__ float scol[128][2];

    const int zb = blockIdx.z;
    const int m0 = blockIdx.y << 7;      // l tile
    const int n0 = blockIdx.x << 7;      // m' tile
    const float* Cb = C + (size_t)zb * D_ * LC;
    const float* Qb = Q + (size_t)zb * D_ * LQ;
    const float* w1 = w, *w2 = w + D_, *w3 = w + 2 * D_;

    const int tid = threadIdx.x, wid = tid >> 5, lane = tid & 31;
    const int wm = (wid >> 2) * 64, wn = (wid & 3) * 32;

    float acc[4][4][4];
#pragma unroll
    for (int i = 0; i < 4; i++)
#pragma unroll
        for (int j = 0; j < 4; j++)
#pragma unroll
            for (int e = 0; e < 4; e++) acc[i][j][e] = 0.f;

    float4 ra[4], rb[4];
    float c1p = 0.f, q2p = 0.f;

    auto ldg = [&](int kk) {
#pragma unroll
        for (int i = 0; i < 4; i++) {
            int v = i * 256 + tid;
            int mn = v & 127, krb = v >> 7;
            int k0i = kk + krb * 4;
            {   // A = C (raw for c1, *w3 for tile)
                const float* p = Cb + (size_t)k0i * LC + m0 + mn;
                float4 x;
                x.x = p[0]; x.y = p[LC]; x.z = p[2 * LC]; x.w = p[3 * LC];
                c1p += x.x * __ldg(w1 + k0i)     + x.y * __ldg(w1 + k0i + 1)
                     + x.z * __ldg(w1 + k0i + 2) + x.w * __ldg(w1 + k0i + 3);
                x.x *= __ldg(w3 + k0i);     x.y *= __ldg(w3 + k0i + 1);
                x.z *= __ldg(w3 + k0i + 2); x.w *= __ldg(w3 + k0i + 3);
                ra[i] = x;
            }
            {   // B = Q (raw; accumulate q2)
                const float* p = Qb + (size_t)k0i * LQ + n0 + mn;
                float4 x;
                x.x = p[0]; x.y = p[LQ]; x.z = p[2 * LQ]; x.w = p[3 * LQ];
                q2p += x.x * __ldg(w2 + k0i)     + x.y * __ldg(w2 + k0i + 1)
                     + x.z * __ldg(w2 + k0i + 2) + x.w * __ldg(w2 + k0i + 3);
                rb[i] = x;
            }
        }
    };
    auto sts = [&]() {
#pragma unroll
        for (int i = 0; i < 4; i++) {
            int v = i * 256 + tid;
            int mn = v & 127, krb = v >> 7;
            int off = mn * FST + krb * 4;
            *reinterpret_cast<float4*>(sA + off) = cvt_sel<true>(ra[i]);
            *reinterpret_cast<float4*>(sB + off) = cvt_sel<true>(rb[i]);
        }
    };

    const uint32_t bA = smem_u32(sA), bB = smem_u32(sB);
    const uint32_t lrow = (uint32_t)(lane & 15) * FST + ((lane >> 4) << 2);

    const int nch = D_ >> 5;   // 4
    ldg(0);
    for (int ch = 0; ch < nch; ch++) {
        sts();
        __syncthreads();
        if (ch + 1 < nch) ldg((ch + 1) << 5);
        MMA_PHASE(bA, bB);
        __syncthreads();
    }

    // reduce bias partials across thread pairs
    sbias[tid >> 7][tid & 127]       = c1p;
    sbias[2 + (tid >> 7)][tid & 127] = q2p;
    __syncthreads();

    // epilogue: E + fused row/col sum partials
    float* Eb = E + (size_t)zb * LC * LQ;
    float cs[8];
#pragma unroll
    for (int j = 0; j < 8; j++) cs[j] = 0.f;

#pragma unroll
    for (int mt = 0; mt < 4; mt++) {
        int rl0 = wm + mt * 16 + (lane >> 2);
        int rl1 = rl0 + 8;
        int r0 = m0 + rl0, r1 = m0 + rl1;
        float br0 = sbias[0][rl0] + sbias[1][rl0];
        float br1 = sbias[0][rl1] + sbias[1][rl1];
        float cm0 = cmask[zb * LC + r0], cm1 = cmask[zb * LC + r1];
        float rs0 = 0.f, rs1 = 0.f;
#pragma unroll
        for (int nt = 0; nt < 4; nt++) {
            int cl = wn + nt * 8 + (lane & 3) * 2;
            int col = n0 + cl;
            float bc0 = sbias[2][cl] + sbias[3][cl];
            float bc1 = sbias[2][cl + 1] + sbias[3][cl + 1];
            float2 v0, v1;
            v0.x = tf32r(__expf(acc[mt][nt][0] + br0 + bc0));
            v0.y = tf32r(__expf(acc[mt][nt][1] + br0 + bc1));
            v1.x = tf32r(__expf(acc[mt][nt][2] + br1 + bc0));
            v1.y = tf32r(__expf(acc[mt][nt][3] + br1 + bc1));
            *reinterpret_cast<float2*>(Eb + (size_t)r0 * LQ + col) = v0;
            *reinterpret_cast<float2*>(Eb + (size_t)r1 * LQ + col) = v1;
            float qa = qmask[zb * LQ + col], qb = qmask[zb * LQ + col + 1];
            rs0 += v0.x * qa + v0.y * qb;
            rs1 += v1.x * qa + v1.y * qb;
            cs[nt * 2 + 0] += v0.x * cm0 + v1.x * cm1;
            cs[nt * 2 + 1] += v0.y * cm0 + v1.y * cm1;
        }
        rs0 += __shfl_xor_sync(0xffffffffu, rs0, 1);
        rs0 += __shfl_xor_sync(0xffffffffu, rs0, 2);
        rs1 += __shfl_xor_sync(0xffffffffu, rs1, 1);
        rs1 += __shfl_xor_sync(0xffffffffu, rs1, 2);
        if ((lane & 3) == 0) {
            srow[rl0][wid & 3] = rs0;
            srow[rl1][wid & 3] = rs1;
        }
    }
#pragma unroll
    for (int j = 0; j < 8; j++) {
        cs[j] += __shfl_xor_sync(0xffffffffu, cs[j], 4);
        cs[j] += __shfl_xor_sync(0xffffffffu, cs[j], 8);
        cs[j] += __shfl_xor_sync(0xffffffffu, cs[j], 16);
    }
    if (lane < 4) {
#pragma unroll
        for (int nt = 0; nt < 4; nt++)
#pragma unroll
            for (int e = 0; e < 2; e++) {
                int cl = wn + nt * 8 + lane * 2 + e;
                scol[cl][wid >> 2] = cs[nt * 2 + e];
            }
    }
    __syncthreads();
    if (tid < 128) {
        float r = srow[tid][0] + srow[tid][1] + srow[tid][2] + srow[tid][3];
        rp[((size_t)zb * 2 + blockIdx.x) * LC + m0 + tid] = r;
        float c = scol[tid][0] + scol[tid][1];
        cp[((size_t)zb * 8 + blockIdx.y) * LQ + n0 + tid] = c;
    }
}

// ---------------- G3: T_raw(m',d) = sum_l E(l,m')*cm(l)*C(d,l) ----------------
__global__ __launch_bounds__(256) void g3(
    const float* __restrict__ E, const float* __restrict__ C,
    const float* __restrict__ cmask, float* __restrict__ T)
{
    __shared__ __align__(16) float sA[128 * FST];
    __shared__ __align__(16) float sB[128 * FST];

    const int zb = blockIdx.z;
    const int m0 = blockIdx.y << 7;
    const float* Eb = E + (size_t)zb * LC * LQ;
    const float* Cb = C + (size_t)zb * D_ * LC;
    const float* cm = cmask + zb * LC;

    const int tid = threadIdx.x, wid = tid >> 5, lane = tid & 31;
    const int wm = (wid >> 2) * 64, wn = (wid & 3) * 32;

    float acc[4][4][4];
#pragma unroll
    for (int i = 0; i < 4; i++)
#pragma unroll
        for (int j = 0; j < 4; j++)
#pragma unroll
            for (int e = 0; e < 4; e++) acc[i][j][e] = 0.f;

    float4 ra[4], rb[4];

    auto ldg = [&](int kk) {
#pragma unroll
        for (int i = 0; i < 4; i++) {
            int v = i * 256 + tid;
            {   // A = E^T (K-slow, pre-rounded)
                int mn = v & 127, krb = v >> 7;
                const float* p = Eb + (size_t)(kk + krb * 4) * LQ + m0 + mn;
                float4 x;
                x.x = p[0]; x.y = p[LQ]; x.z = p[2 * LQ]; x.w = p[3 * LQ];
                ra[i] = x;
            }
            {   // B = C (K-fast) * cmask[k]
                int row = v >> 3, c4 = v & 7;
                float4 x = *reinterpret_cast<const float4*>(Cb + (size_t)row * LC + kk + c4 * 4);
                float4 s = *reinterpret_cast<const float4*>(cm + kk + c4 * 4);
                x.x *= s.x; x.y *= s.y; x.z *= s.z; x.w *= s.w;
                rb[i] = x;
            }
        }
    };
    auto sts = [&]() {
#pragma unroll
        for (int i = 0; i < 4; i++) {
            int v = i * 256 + tid;
            {
                int mn = v & 127, krb = v >> 7;
                *reinterpret_cast<float4*>(sA + mn * FST + krb * 4) = ra[i];
            }
            {
                int row = v >> 3, c4 = v & 7;
                *reinterpret_cast<float4*>(sB + row * FST + c4 * 4) = cvt_sel<true>(rb[i]);
            }
        }
    };

    const uint32_t bA = smem_u32(sA), bB = smem_u32(sB);
    const uint32_t lrow = (uint32_t)(lane & 15) * FST + ((lane >> 4) << 2);

    const int nch = LC >> 5;   // 32
    ldg(0);
    for (int ch = 0; ch < nch; ch++) {
        sts();
        __syncthreads();
        if (ch + 1 < nch) ldg((ch + 1) << 5);
        MMA_PHASE(bA, bB);
        __syncthreads();
    }

    float* Tb = T + (size_t)zb * LQ * D_;
#pragma unroll
    for (int mt = 0; mt < 4; mt++) {
        int r0 = m0 + wm + mt * 16 + (lane >> 2);
        int r1 = r0 + 8;
#pragma unroll
        for (int nt = 0; nt < 4; nt++) {
            int col = wn + nt * 8 + (lane & 3) * 2;
            float2 v0, v1;
            v0.x = acc[mt][nt][0]; v0.y = acc[mt][nt][1];
            v1.x = acc[mt][nt][2]; v1.y = acc[mt][nt][3];
            *reinterpret_cast<float2*>(Tb + (size_t)r0 * D_ + col) = v0;
            *reinterpret_cast<float2*>(Tb + (size_t)r1 * D_ + col) = v1;
        }
    }
}

// ---------------- fused G2+G4 (+finish): A = [Q*qm ; T_raw*qcinv], B = E tile ----------------
__global__ __launch_bounds__(256) void g24(
    const float* __restrict__ Q, const float* __restrict__ T,
    const float* __restrict__ E, const float* __restrict__ C,
    const float* __restrict__ qmask,
    const float* __restrict__ rp, const float* __restrict__ cp,
    float* __restrict__ out)
{
    __shared__ __align__(16) float sA[256 * FST];
    __shared__ __align__(16) float sB[64 * FST];
    __shared__ float sqc[256];   // qcinv
    __shared__ float srv[64];    // rinv for this CTA's l-tile

    const int zb = blockIdx.z;
    const int n0 = blockIdx.x * 64;
    const float* Qb = Q + (size_t)zb * D_ * LQ;
    const float* Tb = T + (size_t)zb * LQ * D_;
    const float* Eb = E + (size_t)zb * LC * LQ;
    const float* qm = qmask + zb * LQ;

    const int tid = threadIdx.x, wid = tid >> 5, lane = tid & 31;
    const int wm = (wid >> 1) * 64, wn = (wid & 1) * 32;

    // prologue: finish reductions (rinv, qcinv) from G1 partials
    if (tid < 64) {
        float s = rp[((size_t)zb * 2 + 0) * LC + n0 + tid]
                + rp[((size_t)zb * 2 + 1) * LC + n0 + tid];
        srv[tid] = 1.f / s;
    }
    {
        float c = 0.f;
#pragma unroll
        for (int y = 0; y < 8; y++) c += cp[((size_t)zb * 8 + y) * LQ + tid];
        sqc[tid] = qm[tid] / c;
    }
    __syncthreads();

    float acc[4][4][4];
#pragma unroll
    for (int i = 0; i < 4; i++)
#pragma unroll
        for (int j = 0; j < 4; j++)
#pragma unroll
            for (int e = 0; e < 4; e++) acc[i][j][e] = 0.f;

    float4 ra[8], rb[2];

    auto ldg = [&](int kk) {
#pragma unroll
        for (int i = 0; i < 4; i++) {                 // Q half, rows 0..127, K-fast
            int v = i * 256 + tid;
            int row = v >> 3, c4 = v & 7;
            float4 x = *reinterpret_cast<const float4*>(Qb + (size_t)row * LQ + kk + c4 * 4);
            float4 s = *reinterpret_cast<const float4*>(qm + kk + c4 * 4);
            x.x *= s.x; x.y *= s.y; x.z *= s.z; x.w *= s.w;
            ra[i] = x;
        }
#pragma unroll
        for (int i = 0; i < 4; i++) {                 // T half, rows 128..255, K-slow, *qcinv
            int v = i * 256 + tid;
            int mn = v & 127, krb = v >> 7;
            int k0i = kk + krb * 4;
            const float* p = Tb + (size_t)k0i * D_ + mn;
            float4 x;
            x.x = p[0] * sqc[k0i];         x.y = p[D_] * sqc[k0i + 1];
            x.z = p[2 * D_] * sqc[k0i + 2]; x.w = p[3 * D_] * sqc[k0i + 3];
            ra[4 + i] = x;
        }
#pragma unroll
        for (int i = 0; i < 2; i++) {                 // E tile, 64 rows (l), pre-rounded
            int v = i * 256 + tid;
            int row = v >> 3, c4 = v & 7;
            rb[i] = *reinterpret_cast<const float4*>(Eb + (size_t)(n0 + row) * LQ + kk + c4 * 4);
        }
    };
    auto sts = [&]() {
#pragma unroll
        for (int i = 0; i < 4; i++) {
            int v = i * 256 + tid;
            int row = v >> 3, c4 = v & 7;
            *reinterpret_cast<float4*>(sA + row * FST + c4 * 4) = cvt_sel<true>(ra[i]);
        }
#pragma unroll
        for (int i = 0; i < 4; i++) {
            int v = i * 256 + tid;
            int mn = v & 127, krb = v >> 7;
            *reinterpret_cast<float4*>(sA + (128 + mn) * FST + krb * 4) = cvt_sel<true>(ra[4 + i]);
        }
#pragma unroll
        for (int i = 0; i < 2; i++) {
            int v = i * 256 + tid;
            int row = v >> 3, c4 = v & 7;
            *reinterpret_cast<float4*>(sB + row * FST + c4 * 4) = rb[i];
        }
    };

    const uint32_t bA = smem_u32(sA), bB = smem_u32(sB);
    const uint32_t lrow = (uint32_t)(lane & 15) * FST + ((lane >> 4) << 2);

    const int nch = LQ >> 5;   // 8
    ldg(0);
    for (int ch = 0; ch < nch; ch++) {
        sts();
        __syncthreads();
        if (ch + 1 < nch) ldg((ch + 1) << 5);
        MMA_PHASE(bA, bB);
        __syncthreads();
    }

    // epilogue: rows < 128 => At (channels 0,1,2); rows >= 128 => Bv (channel 3)
    const float* Cb = C + (size_t)zb * D_ * LC;
    float* O = out + (size_t)zb * 4 * D_ * LC;
#pragma unroll
    for (int mt = 0; mt < 4; mt++) {
        int r0 = wm + mt * 16 + (lane >> 2);
        int r1 = r0 + 8;
#pragma unroll
        for (int nt = 0; nt < 4; nt++) {
            int cl = wn + nt * 8 + (lane & 3) * 2;
            int col = n0 + cl;
            float c0 = srv[cl], c1v = srv[cl + 1];
            float2 v0, v1;
            v0.x = acc[mt][nt][0] * c0; v0.y = acc[mt][nt][1] * c1v;
            v1.x = acc[mt][nt][2] * c0; v1.y = acc[mt][nt][3] * c1v;
            if (wm < 128) {
                int d0 = r0, d1 = r1;
                float2 cc0 = *reinterpret_cast<const float2*>(Cb + (size_t)d0 * LC + col);
                float2 cc1 = *reinterpret_cast<const float2*>(Cb + (size_t)d1 * LC + col);
                *reinterpret_cast<float2*>(O + (size_t)d0 * LC + col) = cc0;
                *reinterpret_cast<float2*>(O + (size_t)d1 * LC + col) = cc1;
                *reinterpret_cast<float2*>(O + (size_t)(D_ + d0) * LC + col) = v0;
                *reinterpret_cast<float2*>(O + (size_t)(D_ + d1) * LC + col) = v1;
                float2 m0v, m1v;
                m0v.x = cc0.x * v0.x; m0v.y = cc0.y * v0.y;
                m1v.x = cc1.x * v1.x; m1v.y = cc1.y * v1.y;
                *reinterpret_cast<float2*>(O + (size_t)(2 * D_ + d0) * LC + col) = m0v;
                *reinterpret_cast<float2*>(O + (size_t)(2 * D_ + d1) * LC + col) = m1v;
            } else {
                int d0 = r0 - 128, d1 = r1 - 128;
                float2 cc0 = *reinterpret_cast<const float2*>(Cb + (size_t)d0 * LC + col);
                float2 cc1 = *reinterpret_cast<const float2*>(Cb + (size_t)d1 * LC + col);
                float2 b0v, b1v;
                b0v.x = cc0.x * v0.x; b0v.y = cc0.y * v0.y;
                b1v.x = cc1.x * v1.x; b1v.y = cc1.y * v1.y;
                *reinterpret_cast<float2*>(O + (size_t)(3 * D_ + d0) * LC + col) = b0v;
                *reinterpret_cast<float2*>(O + (size_t)(3 * D_ + d1) * LC + col) = b1v;
            }
        }
    }
}

// ---------------- launch ----------------
extern "C" void kernel_launch(void* const* d_in, const int* in_sizes, int n_in,
                              void* d_out, int out_size) {
    const float* C     = (const float*)d_in[0];
    const float* Q     = (const float*)d_in[1];
    const float* cmask = (const float*)d_in[2];
    const float* qmask = (const float*)d_in[3];
    const float* w     = (const float*)d_in[4];
    float* out = (float*)d_out;

    float *pE, *pT, *prp, *pcp;
    cudaGetSymbolAddress((void**)&pE,  g_E);
    cudaGetSymbolAddress((void**)&pT,  g_T);
    cudaGetSymbolAddress((void**)&prp, g_rp);
    cudaGetSymbolAddress((void**)&pcp, g_cp);

    // 1: G1 (fused bias + E + sum partials)
    g1<<<dim3(2, 8, B_), 256>>>(C, Q, w, cmask, qmask, pE, prp, pcp);

    // 2: G3
    g3<<<dim3(1, 2, B_), 256>>>(pE, C, cmask, pT);

    // 3: fused G2+G4 (+finish) + output assembly
    g24<<<dim3(LC / 64, 1, B_), 256>>>(Q, pT, pE, C, qmask, prp, pcp, out);
}